// round 7
// baseline (speedup 1.0000x reference)
#include <cuda_runtime.h>
#include <math.h>
#include <cstdint>

// Problem constants
#define T_SEQ 4096
#define D_MODEL 2048
#define N_HEADS 16
#define N_KV 4
#define DH 128
#define HALF 64
#define KV_DIM 512   // N_KV * DH

typedef unsigned long long ull;

// Scratch (device globals; no allocation allowed)
__device__ float g_q[T_SEQ * D_MODEL];
__device__ float g_k[T_SEQ * KV_DIM];
__device__ float g_v[T_SEQ * KV_DIM];
__device__ float g_y[T_SEQ * D_MODEL];

// ---------------------------------------------------------------------------
// Packed f32x2 helpers
// ---------------------------------------------------------------------------
__device__ __forceinline__ ull ffma2(ull a, ull b, ull c) {
    ull d;
    asm("fma.rn.f32x2 %0, %1, %2, %3;" : "=l"(d) : "l"(a), "l"(b), "l"(c));
    return d;
}
__device__ __forceinline__ ull mul2(ull a, ull b) {
    ull d;
    asm("mul.rn.f32x2 %0, %1, %2;" : "=l"(d) : "l"(a), "l"(b));
    return d;
}
__device__ __forceinline__ ull bcast2(float x) {
    ull d;
    asm("mov.b64 %0, {%1, %1};" : "=l"(d) : "f"(x));
    return d;
}

// ---------------------------------------------------------------------------
// tf32 mma.sync helpers (plain sm_80+ PTX, assembles for sm_103)
// ---------------------------------------------------------------------------
__device__ __forceinline__ uint32_t cvt_tf32(float f) {
    uint32_t u;
    asm("cvt.rna.tf32.f32 %0, %1;" : "=r"(u) : "f"(f));
    return u;
}

__device__ __forceinline__ void mma_tf32(float* d, const uint32_t* a,
                                         const uint32_t* b, const float* c) {
    asm volatile(
        "mma.sync.aligned.m16n8k8.row.col.f32.tf32.tf32.f32 "
        "{%0,%1,%2,%3}, {%4,%5,%6,%7}, {%8,%9}, {%10,%11,%12,%13};"
        : "=f"(d[0]), "=f"(d[1]), "=f"(d[2]), "=f"(d[3])
        : "r"(a[0]), "r"(a[1]), "r"(a[2]), "r"(a[3]),
          "r"(b[0]), "r"(b[1]),
          "f"(c[0]), "f"(c[1]), "f"(c[2]), "f"(c[3]));
}

// ---------------------------------------------------------------------------
// TF32 tensor-core GEMM: C[M,N] = A[M,K] @ B[K,N], fp32 in/out. (unchanged R6)
// ---------------------------------------------------------------------------
__global__ __launch_bounds__(256)
void sgemm_tf32(const float* __restrict__ A, const float* __restrict__ B,
                float* __restrict__ C, int M, int N, int K) {
    __shared__ uint32_t As[128][20];    // [m][k], +4 pad
    __shared__ uint32_t Bs[16][132];    // [k][n], +4 pad

    const int tid = threadIdx.x;
    const int wid = tid >> 5;
    const int lane = tid & 31;
    const int g = lane >> 2;
    const int t = lane & 3;
    const int m0 = blockIdx.y * 128;
    const int n0 = blockIdx.x * 128;
    const int wm = (wid & 3) * 32;
    const int wn = (wid >> 2) * 64;

    float acc[2][8][4];
#pragma unroll
    for (int mt = 0; mt < 2; ++mt)
#pragma unroll
        for (int nt = 0; nt < 8; ++nt)
#pragma unroll
            for (int r = 0; r < 4; ++r) acc[mt][nt][r] = 0.f;

    for (int k0 = 0; k0 < K; k0 += 16) {
#pragma unroll
        for (int l = 0; l < 2; ++l) {
            int idx = tid + l * 256;
            int row = idx >> 2;
            int k4 = (idx & 3) << 2;
            float4 v = *(const float4*)(A + (size_t)(m0 + row) * K + k0 + k4);
            uint4 u;
            u.x = cvt_tf32(v.x); u.y = cvt_tf32(v.y);
            u.z = cvt_tf32(v.z); u.w = cvt_tf32(v.w);
            *(uint4*)(&As[row][k4]) = u;
        }
#pragma unroll
        for (int l = 0; l < 2; ++l) {
            int idx = tid + l * 256;
            int kk = idx >> 5;
            int n4 = (idx & 31) << 2;
            float4 v = *(const float4*)(B + (size_t)(k0 + kk) * N + n0 + n4);
            uint4 u;
            u.x = cvt_tf32(v.x); u.y = cvt_tf32(v.y);
            u.z = cvt_tf32(v.z); u.w = cvt_tf32(v.w);
            *(uint4*)(&Bs[kk][n4]) = u;
        }
        __syncthreads();

#pragma unroll
        for (int ks = 0; ks < 2; ++ks) {
            const int kk = ks * 8;
            uint32_t af[2][4];
#pragma unroll
            for (int mt = 0; mt < 2; ++mt) {
                const int r0 = wm + mt * 16;
                af[mt][0] = As[r0 + g][kk + t];
                af[mt][1] = As[r0 + g + 8][kk + t];
                af[mt][2] = As[r0 + g][kk + t + 4];
                af[mt][3] = As[r0 + g + 8][kk + t + 4];
            }
            uint32_t bf[8][2];
#pragma unroll
            for (int nt = 0; nt < 8; ++nt) {
                bf[nt][0] = Bs[kk + t][wn + nt * 8 + g];
                bf[nt][1] = Bs[kk + t + 4][wn + nt * 8 + g];
            }
#pragma unroll
            for (int mt = 0; mt < 2; ++mt)
#pragma unroll
                for (int nt = 0; nt < 8; ++nt)
                    mma_tf32(acc[mt][nt], af[mt], bf[nt], acc[mt][nt]);
        }
        __syncthreads();
    }

#pragma unroll
    for (int mt = 0; mt < 2; ++mt) {
        const int r0 = m0 + wm + mt * 16;
#pragma unroll
        for (int nt = 0; nt < 8; ++nt) {
            const int c0 = n0 + wn + nt * 8 + t * 2;
            *(float2*)(C + (size_t)(r0 + g) * N + c0) =
                make_float2(acc[mt][nt][0], acc[mt][nt][1]);
            *(float2*)(C + (size_t)(r0 + g + 8) * N + c0) =
                make_float2(acc[mt][nt][2], acc[mt][nt][3]);
        }
    }
}

// ---------------------------------------------------------------------------
// RoPE in-place on [T, nheads, 128] buffers (rowstride = nheads*128)
// ---------------------------------------------------------------------------
__global__ void rope_kernel(float* __restrict__ buf, int nheads, int rowstride) {
    int idx = blockIdx.x * blockDim.x + threadIdx.x;
    int total = T_SEQ * nheads * HALF;
    if (idx >= total) return;
    int i = idx & (HALF - 1);
    int h = (idx >> 6) % nheads;
    int t = idx / (HALF * nheads);

    float inv = powf(10000.f, -(float)i / (float)HALF);
    float ang = (float)t * inv;
    float s, c;
    sincosf(ang, &s, &c);

    float* base = buf + (size_t)t * rowstride + h * DH;
    float x1 = base[i];
    float x2 = base[i + HALF];
    base[i]        = x1 * c - x2 * s;
    base[i + HALF] = x1 * s + x2 * c;
}

// ---------------------------------------------------------------------------
// Flash attention v2: S = QK^T on tensor cores (tf32 mma.sync), softmax fp32,
// PV exact fp32 via f32x2 FFMA. CTA = 128 queries x 1 head, 8 warps x 16 rows,
// key blocks of 64. Strides chosen so every fragment LDS is conflict-free.
// ---------------------------------------------------------------------------
#define AQ_S 132   // Qs row stride (u32):  g*4+t banks, conflict-free frags
#define AK_S 136   // Ks row stride (u32):  g*8+t banks, conflict-free frags
#define AV_S 132   // Vs row stride (fp32)
#define AP_S 68    // P  row stride (fp32): g*4+key banks

#define OFF_Q 0
#define OFF_K (128 * AQ_S)
#define OFF_V (OFF_K + 64 * AK_S)
#define OFF_P (OFF_V + 64 * AV_S)
#define ATTN_SMEM_BYTES ((OFF_P + 8 * 16 * AP_S) * 4)

__global__ __launch_bounds__(256)
void attn_mma(const float* __restrict__ q, const float* __restrict__ k,
              const float* __restrict__ v, float* __restrict__ y) {
    extern __shared__ uint32_t sm4[];
    uint32_t* Qs = sm4 + OFF_Q;           // [128 q][AQ_S] tf32 bits
    uint32_t* Ks = sm4 + OFF_K;           // [64 key][AK_S] tf32 bits
    float*    Vs = (float*)(sm4 + OFF_V); // [64 key][AV_S] fp32
    float*    Ps = (float*)(sm4 + OFF_P); // per warp [16][AP_S] fp32

    const int qb = (gridDim.x - 1) - blockIdx.x;   // heavy blocks first
    const int hq = blockIdx.y;
    const int hkv = hq >> 2;
    const int q0 = qb * 128;
    const int tid = threadIdx.x;
    const int wid = tid >> 5;
    const int lane = tid & 31;
    const int g = lane >> 2;
    const int t = lane & 3;
    const int wm = wid * 16;
    float* Pw = Ps + wid * 16 * AP_S;

    // ---- stage Q (128 x 128) as tf32, once per CTA
#pragma unroll
    for (int l = 0; l < 16; ++l) {
        int lin = tid + l * 256;
        int row = lin >> 5;
        int c4 = (lin & 31) << 2;
        float4 val = *(const float4*)(q + (size_t)(q0 + row) * D_MODEL + hq * DH + c4);
        uint4 u;
        u.x = cvt_tf32(val.x); u.y = cvt_tf32(val.y);
        u.z = cvt_tf32(val.z); u.w = cvt_tf32(val.w);
        *(uint4*)(Qs + row * AQ_S + c4) = u;
    }

    // O accumulators: rows {g, g+8} of this warp's 16-row span, cols t*32..t*32+31
    ull o2[2][16];
#pragma unroll
    for (int r = 0; r < 2; ++r)
#pragma unroll
        for (int j = 0; j < 16; ++j) o2[r][j] = 0ull;
    float mrow[2] = {-1e30f, -1e30f};
    float lrow[2] = {0.f, 0.f};

    const float scale = 0.08838834764831845f;   // 1/sqrt(128)
    const int rg0 = q0 + wm + g;
    const int rg1 = rg0 + 8;

    const int nkb = 2 * qb + 2;
    for (int kb = 0; kb < nkb; ++kb) {
        const int j0 = kb * 64;
        __syncthreads();   // previous tile fully consumed

        // ---- stage K (tf32) + V (fp32), 64 x 128 each
#pragma unroll
        for (int l = 0; l < 8; ++l) {
            int lin = tid + l * 256;
            int row = lin >> 5;
            int c4 = (lin & 31) << 2;
            float4 kv = *(const float4*)(k + (size_t)(j0 + row) * KV_DIM + hkv * DH + c4);
            uint4 u;
            u.x = cvt_tf32(kv.x); u.y = cvt_tf32(kv.y);
            u.z = cvt_tf32(kv.z); u.w = cvt_tf32(kv.w);
            *(uint4*)(Ks + row * AK_S + c4) = u;
            float4 vv = *(const float4*)(v + (size_t)(j0 + row) * KV_DIM + hkv * DH + c4);
            *(float4*)(Vs + row * AV_S + c4) = vv;
        }
        __syncthreads();

        // warps whose rows are entirely above this key block skip compute
        if (j0 <= q0 + wm + 15) {
            // ---- S = Q K^T : 1 m-tile x 8 n-tiles, 16 k8-steps
            float s[8][4];
#pragma unroll
            for (int nt = 0; nt < 8; ++nt)
#pragma unroll
                for (int r = 0; r < 4; ++r) s[nt][r] = 0.f;

            const uint32_t* qr0 = Qs + (wm + g) * AQ_S;
            const uint32_t* qr1 = Qs + (wm + g + 8) * AQ_S;
#pragma unroll
            for (int ks = 0; ks < 16; ++ks) {
                const int kk = ks * 8;
                uint32_t a[4] = {qr0[kk + t], qr1[kk + t], qr0[kk + t + 4], qr1[kk + t + 4]};
#pragma unroll
                for (int nt = 0; nt < 8; ++nt) {
                    uint32_t b[2] = {Ks[(nt * 8 + g) * AK_S + kk + t],
                                     Ks[(nt * 8 + g) * AK_S + kk + t + 4]};
                    mma_tf32(s[nt], a, b, s[nt]);
                }
            }

            // ---- scale + causal mask (last two key blocks only)
            const bool diag = (kb >= 2 * qb);
#pragma unroll
            for (int nt = 0; nt < 8; ++nt) {
                const int c = j0 + nt * 8 + t * 2;
                s[nt][0] *= scale; s[nt][1] *= scale;
                s[nt][2] *= scale; s[nt][3] *= scale;
                if (diag) {
                    if (c     > rg0) s[nt][0] = -1e30f;
                    if (c + 1 > rg0) s[nt][1] = -1e30f;
                    if (c     > rg1) s[nt][2] = -1e30f;
                    if (c + 1 > rg1) s[nt][3] = -1e30f;
                }
            }

            // ---- online softmax for rows rg0, rg1 (quad = lanes sharing g)
            float mx0 = -1e30f, mx1 = -1e30f;
#pragma unroll
            for (int nt = 0; nt < 8; ++nt) {
                mx0 = fmaxf(mx0, fmaxf(s[nt][0], s[nt][1]));
                mx1 = fmaxf(mx1, fmaxf(s[nt][2], s[nt][3]));
            }
            mx0 = fmaxf(mx0, __shfl_xor_sync(0xffffffffu, mx0, 1));
            mx0 = fmaxf(mx0, __shfl_xor_sync(0xffffffffu, mx0, 2));
            mx1 = fmaxf(mx1, __shfl_xor_sync(0xffffffffu, mx1, 1));
            mx1 = fmaxf(mx1, __shfl_xor_sync(0xffffffffu, mx1, 2));

            const float mn0 = fmaxf(mrow[0], mx0);
            const float mn1 = fmaxf(mrow[1], mx1);
            const float al0 = __expf(mrow[0] - mn0);
            const float al1 = __expf(mrow[1] - mn1);

            float sum0 = 0.f, sum1 = 0.f;
#pragma unroll
            for (int nt = 0; nt < 8; ++nt) {
                s[nt][0] = __expf(s[nt][0] - mn0);
                s[nt][1] = __expf(s[nt][1] - mn0);
                s[nt][2] = __expf(s[nt][2] - mn1);
                s[nt][3] = __expf(s[nt][3] - mn1);
                sum0 += s[nt][0] + s[nt][1];
                sum1 += s[nt][2] + s[nt][3];
            }
            sum0 += __shfl_xor_sync(0xffffffffu, sum0, 1);
            sum0 += __shfl_xor_sync(0xffffffffu, sum0, 2);
            sum1 += __shfl_xor_sync(0xffffffffu, sum1, 1);
            sum1 += __shfl_xor_sync(0xffffffffu, sum1, 2);

            lrow[0] = lrow[0] * al0 + sum0;
            lrow[1] = lrow[1] * al1 + sum1;
            mrow[0] = mn0;
            mrow[1] = mn1;

            const ull a0 = bcast2(al0), a1 = bcast2(al1);
#pragma unroll
            for (int j = 0; j < 16; ++j) {
                o2[0][j] = mul2(o2[0][j], a0);
                o2[1][j] = mul2(o2[1][j], a1);
            }

            // ---- store P (fp32) to this warp's region
#pragma unroll
            for (int nt = 0; nt < 8; ++nt) {
                *(float2*)(Pw + g * AP_S + nt * 8 + t * 2) =
                    make_float2(s[nt][0], s[nt][1]);
                *(float2*)(Pw + (g + 8) * AP_S + nt * 8 + t * 2) =
                    make_float2(s[nt][2], s[nt][3]);
            }
            __syncwarp();

            // ---- O += P V  (exact fp32, f32x2 packed)
#pragma unroll 2
            for (int key = 0; key < 64; ++key) {
                const ull p0 = bcast2(Pw[g * AP_S + key]);
                const ull p1 = bcast2(Pw[(g + 8) * AP_S + key]);
                const float* vr = Vs + key * AV_S + t * 32;
#pragma unroll
                for (int j = 0; j < 8; ++j) {
                    ulonglong2 vv = *(const ulonglong2*)(vr + j * 4);
                    o2[0][j * 2]     = ffma2(p0, vv.x, o2[0][j * 2]);
                    o2[0][j * 2 + 1] = ffma2(p0, vv.y, o2[0][j * 2 + 1]);
                    o2[1][j * 2]     = ffma2(p1, vv.x, o2[1][j * 2]);
                    o2[1][j * 2 + 1] = ffma2(p1, vv.y, o2[1][j * 2 + 1]);
                }
            }
        }
    }

    // ---- normalize + write
    const ull i0 = bcast2(1.f / lrow[0]);
    const ull i1 = bcast2(1.f / lrow[1]);
    float* y0 = y + (size_t)rg0 * D_MODEL + hq * DH + t * 32;
    float* y1 = y + (size_t)rg1 * D_MODEL + hq * DH + t * 32;
#pragma unroll
    for (int j = 0; j < 8; ++j) {
        ulonglong2 w0, w1;
        w0.x = mul2(o2[0][j * 2], i0); w0.y = mul2(o2[0][j * 2 + 1], i0);
        w1.x = mul2(o2[1][j * 2], i1); w1.y = mul2(o2[1][j * 2 + 1], i1);
        *(ulonglong2*)(y0 + j * 4) = w0;
        *(ulonglong2*)(y1 + j * 4) = w1;
    }
}

// ---------------------------------------------------------------------------
extern "C" void kernel_launch(void* const* d_in, const int* in_sizes, int n_in,
                              void* d_out, int out_size) {
    const float* x  = (const float*)d_in[0];
    const float* Wq = (const float*)d_in[1];
    const float* Wk = (const float*)d_in[2];
    const float* Wv = (const float*)d_in[3];
    const float* Wo = (const float*)d_in[4];
    float* out = (float*)d_out;

    void *pq, *pk, *pv, *py;
    cudaGetSymbolAddress(&pq, g_q);
    cudaGetSymbolAddress(&pk, g_k);
    cudaGetSymbolAddress(&pv, g_v);
    cudaGetSymbolAddress(&py, g_y);
    float* q = (float*)pq;
    float* kf = (float*)pk;
    float* vf = (float*)pv;
    float* y = (float*)py;

    // Projections (tf32 tensor cores via mma.sync)
    sgemm_tf32<<<dim3(D_MODEL / 128, T_SEQ / 128), 256>>>(x, Wq, q, T_SEQ, D_MODEL, D_MODEL);
    sgemm_tf32<<<dim3(KV_DIM / 128, T_SEQ / 128), 256>>>(x, Wk, kf, T_SEQ, KV_DIM, D_MODEL);
    sgemm_tf32<<<dim3(KV_DIM / 128, T_SEQ / 128), 256>>>(x, Wv, vf, T_SEQ, KV_DIM, D_MODEL);

    // RoPE
    {
        int nq = T_SEQ * N_HEADS * HALF;
        rope_kernel<<<(nq + 255) / 256, 256>>>(q, N_HEADS, D_MODEL);
        int nk = T_SEQ * N_KV * HALF;
        rope_kernel<<<(nk + 255) / 256, 256>>>(kf, N_KV, KV_DIM);
    }

    // Attention (tensor-core S, exact fp32 PV)
    cudaFuncSetAttribute(attn_mma, cudaFuncAttributeMaxDynamicSharedMemorySize, ATTN_SMEM_BYTES);
    attn_mma<<<dim3(T_SEQ / 128, N_HEADS), 256, ATTN_SMEM_BYTES>>>(q, kf, vf, y);

    // Output projection
    sgemm_tf32<<<dim3(D_MODEL / 128, T_SEQ / 128), 256>>>(y, Wo, out, T_SEQ, D_MODEL, D_MODEL);
}

// round 8
// speedup vs baseline: 2.2217x; 2.2217x over previous
#include <cuda_runtime.h>
#include <math.h>
#include <cstdint>

// Problem constants
#define T_SEQ 4096
#define D_MODEL 2048
#define N_HEADS 16
#define N_KV 4
#define DH 128
#define HALF 64
#define KV_DIM 512   // N_KV * DH

typedef unsigned long long ull;

// Scratch (device globals; no allocation allowed)
__device__ float g_q[T_SEQ * D_MODEL];
__device__ float g_k[T_SEQ * KV_DIM];
__device__ float g_v[T_SEQ * KV_DIM];
__device__ float g_y[T_SEQ * D_MODEL];

// ---------------------------------------------------------------------------
// Packed f32x2 helpers
// ---------------------------------------------------------------------------
__device__ __forceinline__ ull ffma2(ull a, ull b, ull c) {
    ull d;
    asm("fma.rn.f32x2 %0, %1, %2, %3;" : "=l"(d) : "l"(a), "l"(b), "l"(c));
    return d;
}
__device__ __forceinline__ ull mul2(ull a, ull b) {
    ull d;
    asm("mul.rn.f32x2 %0, %1, %2;" : "=l"(d) : "l"(a), "l"(b));
    return d;
}
__device__ __forceinline__ ull bcast2(float x) {
    ull d;
    asm("mov.b64 %0, {%1, %1};" : "=l"(d) : "f"(x));
    return d;
}
union F2U { ull u; float2 f; };

// ---------------------------------------------------------------------------
// tf32 mma.sync helpers
// ---------------------------------------------------------------------------
__device__ __forceinline__ uint32_t cvt_tf32(float f) {
    uint32_t u;
    asm("cvt.rna.tf32.f32 %0, %1;" : "=r"(u) : "f"(f));
    return u;
}

__device__ __forceinline__ void mma_tf32(float* d, const uint32_t* a,
                                         const uint32_t* b, const float* c) {
    asm volatile(
        "mma.sync.aligned.m16n8k8.row.col.f32.tf32.tf32.f32 "
        "{%0,%1,%2,%3}, {%4,%5,%6,%7}, {%8,%9}, {%10,%11,%12,%13};"
        : "=f"(d[0]), "=f"(d[1]), "=f"(d[2]), "=f"(d[3])
        : "r"(a[0]), "r"(a[1]), "r"(a[2]), "r"(a[3]),
          "r"(b[0]), "r"(b[1]),
          "f"(c[0]), "f"(c[1]), "f"(c[2]), "f"(c[3]));
}

// ---------------------------------------------------------------------------
// TF32 tensor-core GEMM, software-pipelined (double-buffered smem).
// C[M,N] = A[M,K] @ B[K,N], fp32 in/out.
// CTA 128x128, BK=16, 256 threads = 8 warps (4m x 2n), warp tile 32x64.
// ---------------------------------------------------------------------------
__global__ __launch_bounds__(256, 2)
void sgemm_tf32(const float* __restrict__ A, const float* __restrict__ B,
                float* __restrict__ C, int M, int N, int K) {
    __shared__ uint32_t As[2][128][20];    // [buf][m][k], +4 pad
    __shared__ uint32_t Bs[2][16][132];    // [buf][k][n], +4 pad

    const int tid = threadIdx.x;
    const int wid = tid >> 5;
    const int lane = tid & 31;
    const int g = lane >> 2;
    const int t = lane & 3;
    const int m0 = blockIdx.y * 128;
    const int n0 = blockIdx.x * 128;
    const int wm = (wid & 3) * 32;
    const int wn = (wid >> 2) * 64;

    // staging indices (constant per thread)
    const int aRow0 = tid >> 2;            // l=0 row
    const int aK4   = (tid & 3) << 2;
    const int bK0   = tid >> 5;            // l=0 k-row
    const int bN4   = (tid & 31) << 2;

    float acc[2][8][4];
#pragma unroll
    for (int mt = 0; mt < 2; ++mt)
#pragma unroll
        for (int nt = 0; nt < 8; ++nt)
#pragma unroll
            for (int r = 0; r < 4; ++r) acc[mt][nt][r] = 0.f;

    float4 ar[2], br[2];

    // ---- prologue: load tile 0
#pragma unroll
    for (int l = 0; l < 2; ++l) {
        ar[l] = *(const float4*)(A + (size_t)(m0 + aRow0 + l * 64) * K + aK4);
        br[l] = *(const float4*)(B + (size_t)(bK0 + l * 8) * N + n0 + bN4);
    }
#pragma unroll
    for (int l = 0; l < 2; ++l) {
        uint4 u;
        u.x = cvt_tf32(ar[l].x); u.y = cvt_tf32(ar[l].y);
        u.z = cvt_tf32(ar[l].z); u.w = cvt_tf32(ar[l].w);
        *(uint4*)(&As[0][aRow0 + l * 64][aK4]) = u;
        uint4 w;
        w.x = cvt_tf32(br[l].x); w.y = cvt_tf32(br[l].y);
        w.z = cvt_tf32(br[l].z); w.w = cvt_tf32(br[l].w);
        *(uint4*)(&Bs[0][bK0 + l * 8][bN4]) = w;
    }
    __syncthreads();

    const int KT = K >> 4;
    for (int kt = 0; kt < KT; ++kt) {
        const int buf = kt & 1;

        // ---- prefetch tile kt+1 (global -> regs), overlaps with MMA below
        if (kt + 1 < KT) {
            const int k0n = (kt + 1) << 4;
#pragma unroll
            for (int l = 0; l < 2; ++l) {
                ar[l] = *(const float4*)(A + (size_t)(m0 + aRow0 + l * 64) * K + k0n + aK4);
                br[l] = *(const float4*)(B + (size_t)(k0n + bK0 + l * 8) * N + n0 + bN4);
            }
        }

        // ---- compute tile kt: two k8 steps
#pragma unroll
        for (int ks = 0; ks < 2; ++ks) {
            const int kk = ks * 8;
            uint32_t af[2][4];
#pragma unroll
            for (int mt = 0; mt < 2; ++mt) {
                const int r0 = wm + mt * 16;
                af[mt][0] = As[buf][r0 + g][kk + t];
                af[mt][1] = As[buf][r0 + g + 8][kk + t];
                af[mt][2] = As[buf][r0 + g][kk + t + 4];
                af[mt][3] = As[buf][r0 + g + 8][kk + t + 4];
            }
            uint32_t bf[8][2];
#pragma unroll
            for (int nt = 0; nt < 8; ++nt) {
                bf[nt][0] = Bs[buf][kk + t][wn + nt * 8 + g];
                bf[nt][1] = Bs[buf][kk + t + 4][wn + nt * 8 + g];
            }
#pragma unroll
            for (int mt = 0; mt < 2; ++mt)
#pragma unroll
                for (int nt = 0; nt < 8; ++nt)
                    mma_tf32(acc[mt][nt], af[mt], bf[nt], acc[mt][nt]);
        }

        // ---- stage tile kt+1 into the other buffer
        if (kt + 1 < KT) {
            const int nb = buf ^ 1;
#pragma unroll
            for (int l = 0; l < 2; ++l) {
                uint4 u;
                u.x = cvt_tf32(ar[l].x); u.y = cvt_tf32(ar[l].y);
                u.z = cvt_tf32(ar[l].z); u.w = cvt_tf32(ar[l].w);
                *(uint4*)(&As[nb][aRow0 + l * 64][aK4]) = u;
                uint4 w;
                w.x = cvt_tf32(br[l].x); w.y = cvt_tf32(br[l].y);
                w.z = cvt_tf32(br[l].z); w.w = cvt_tf32(br[l].w);
                *(uint4*)(&Bs[nb][bK0 + l * 8][bN4]) = w;
            }
            __syncthreads();
        }
    }

    // ---- epilogue
#pragma unroll
    for (int mt = 0; mt < 2; ++mt) {
        const int r0 = m0 + wm + mt * 16;
#pragma unroll
        for (int nt = 0; nt < 8; ++nt) {
            const int c0 = n0 + wn + nt * 8 + t * 2;
            *(float2*)(C + (size_t)(r0 + g) * N + c0) =
                make_float2(acc[mt][nt][0], acc[mt][nt][1]);
            *(float2*)(C + (size_t)(r0 + g + 8) * N + c0) =
                make_float2(acc[mt][nt][2], acc[mt][nt][3]);
        }
    }
}

// ---------------------------------------------------------------------------
// RoPE in-place on [T, nheads, 128] buffers (rowstride = nheads*128)
// ---------------------------------------------------------------------------
__global__ void rope_kernel(float* __restrict__ buf, int nheads, int rowstride) {
    int idx = blockIdx.x * blockDim.x + threadIdx.x;
    int total = T_SEQ * nheads * HALF;
    if (idx >= total) return;
    int i = idx & (HALF - 1);
    int h = (idx >> 6) % nheads;
    int t = idx / (HALF * nheads);

    float inv = powf(10000.f, -(float)i / (float)HALF);
    float ang = (float)t * inv;
    float s, c;
    sincosf(ang, &s, &c);

    float* base = buf + (size_t)t * rowstride + h * DH;
    float x1 = base[i];
    float x2 = base[i + HALF];
    base[i]        = x1 * c - x2 * s;
    base[i + HALF] = x1 * s + x2 * c;
}

// ---------------------------------------------------------------------------
// Flash attention (causal, GQA) — R3 version (known good, ~1.75ms)
// ---------------------------------------------------------------------------
#define QT_OFF 0
#define KT_OFF 8192
#define VS_OFF 16384
#define PT_OFF 24576
#define SMEM_FLOATS (24576 + 64 * 68)
#define SMEM_BYTES (SMEM_FLOATS * 4)

__global__ __launch_bounds__(256)
void attn_kernel(const float* __restrict__ q, const float* __restrict__ k,
                 const float* __restrict__ v, float* __restrict__ y) {
    extern __shared__ float sm[];
    float* Qt = sm + QT_OFF;
    float* Kt = sm + KT_OFF;
    float* Vs = sm + VS_OFF;
    float* Pt = sm + PT_OFF;

    const int qb = blockIdx.x;
    const int hq = blockIdx.y;
    const int hkv = hq >> 2;
    const int tid = threadIdx.x;
    const int tx = tid & 15;
    const int ty = tid >> 4;
    const int q0 = qb * 64;

#pragma unroll
    for (int l = 0; l < 8; ++l) {
        int lin = tid + l * 256;
        int r = lin >> 5;
        int d4 = lin & 31;
        int d = d4 << 2;
        float4 val = *(const float4*)(q + (size_t)(q0 + r) * D_MODEL + hq * DH + d);
        int g = r >> 2, ci = r & 3;
        int gs = (g ^ (d4 & 15)) << 2;
        Qt[(d + 0) * 64 + gs + ci] = val.x;
        Qt[(d + 1) * 64 + gs + ci] = val.y;
        Qt[(d + 2) * 64 + gs + ci] = val.z;
        Qt[(d + 3) * 64 + gs + ci] = val.w;
    }

    float m_i[4], l_i[4];
    ull acc2[4][4];
#pragma unroll
    for (int i = 0; i < 4; ++i) {
        m_i[i] = -1e30f;
        l_i[i] = 0.f;
#pragma unroll
        for (int j = 0; j < 4; ++j) acc2[i][j] = 0ull;
    }

    const float scale = 0.08838834764831845f;

    for (int jb = 0; jb <= qb; ++jb) {
        const int j0 = jb * 64;
        __syncthreads();

#pragma unroll
        for (int l = 0; l < 8; ++l) {
            int lin = tid + l * 256;
            int r = lin >> 5;
            int d4 = lin & 31;
            int d = d4 << 2;
            float4 kv4 = *(const float4*)(k + (size_t)(j0 + r) * KV_DIM + hkv * DH + d);
            int g = r >> 2, ci = r & 3;
            int gs = (g ^ (d4 & 15)) << 2;
            Kt[(d + 0) * 64 + gs + ci] = kv4.x;
            Kt[(d + 1) * 64 + gs + ci] = kv4.y;
            Kt[(d + 2) * 64 + gs + ci] = kv4.z;
            Kt[(d + 3) * 64 + gs + ci] = kv4.w;
            float4 vv4 = *(const float4*)(v + (size_t)(j0 + r) * KV_DIM + hkv * DH + d);
            *(float4*)(Vs + r * 128 + d) = vv4;
        }
        __syncthreads();

        ull s2[4][2];
#pragma unroll
        for (int i = 0; i < 4; ++i) { s2[i][0] = 0ull; s2[i][1] = 0ull; }

#pragma unroll 4
        for (int d = 0; d < 128; ++d) {
            int d4 = d >> 2;
            float4 a = *(float4*)(Qt + d * 64 + ((ty ^ (d4 & 15)) << 2));
            ulonglong2 b = *(ulonglong2*)(Kt + d * 64 + ((tx ^ (d4 & 15)) << 2));
            ull a0 = bcast2(a.x), a1 = bcast2(a.y), a2 = bcast2(a.z), a3 = bcast2(a.w);
            s2[0][0] = ffma2(a0, b.x, s2[0][0]); s2[0][1] = ffma2(a0, b.y, s2[0][1]);
            s2[1][0] = ffma2(a1, b.x, s2[1][0]); s2[1][1] = ffma2(a1, b.y, s2[1][1]);
            s2[2][0] = ffma2(a2, b.x, s2[2][0]); s2[2][1] = ffma2(a2, b.y, s2[2][1]);
            s2[3][0] = ffma2(a3, b.x, s2[3][0]); s2[3][1] = ffma2(a3, b.y, s2[3][1]);
        }

        float s[4][4];
        const bool diag = (jb == qb);
#pragma unroll
        for (int i = 0; i < 4; ++i) {
            F2U t0, t1;
            t0.u = s2[i][0]; t1.u = s2[i][1];
            s[i][0] = t0.f.x; s[i][1] = t0.f.y; s[i][2] = t1.f.x; s[i][3] = t1.f.y;
            int rl = ty * 4 + i;
#pragma unroll
            for (int j = 0; j < 4; ++j) {
                int cl = tx * 4 + j;
                float sv = s[i][j] * scale;
                if (diag && cl > rl) sv = -1e30f;
                s[i][j] = sv;
            }
        }

#pragma unroll
        for (int i = 0; i < 4; ++i) {
            float mx = fmaxf(fmaxf(s[i][0], s[i][1]), fmaxf(s[i][2], s[i][3]));
#pragma unroll
            for (int off = 1; off < 16; off <<= 1)
                mx = fmaxf(mx, __shfl_xor_sync(0xffffffffu, mx, off));
            float mnew = fmaxf(m_i[i], mx);
            float alpha = __expf(m_i[i] - mnew);
            float rs = 0.f;
#pragma unroll
            for (int j = 0; j < 4; ++j) {
                float p = __expf(s[i][j] - mnew);
                s[i][j] = p;
                rs += p;
            }
#pragma unroll
            for (int off = 1; off < 16; off <<= 1)
                rs += __shfl_xor_sync(0xffffffffu, rs, off);
            l_i[i] = l_i[i] * alpha + rs;
            m_i[i] = mnew;
            ull al2 = bcast2(alpha);
#pragma unroll
            for (int j = 0; j < 4; ++j) acc2[i][j] = mul2(acc2[i][j], al2);
        }

#pragma unroll
        for (int j = 0; j < 4; ++j) {
            *(float4*)(Pt + (tx * 4 + j) * 68 + ty * 4) =
                make_float4(s[0][j], s[1][j], s[2][j], s[3][j]);
        }
        __syncthreads();

#pragma unroll 4
        for (int c = 0; c < 64; ++c) {
            float4 a = *(float4*)(Pt + c * 68 + ty * 4);
            ulonglong2 b0 = *(ulonglong2*)(Vs + c * 128 + tx * 4);
            ulonglong2 b1 = *(ulonglong2*)(Vs + c * 128 + 64 + tx * 4);
            ull av[4] = {bcast2(a.x), bcast2(a.y), bcast2(a.z), bcast2(a.w)};
#pragma unroll
            for (int i = 0; i < 4; ++i) {
                acc2[i][0] = ffma2(av[i], b0.x, acc2[i][0]);
                acc2[i][1] = ffma2(av[i], b0.y, acc2[i][1]);
                acc2[i][2] = ffma2(av[i], b1.x, acc2[i][2]);
                acc2[i][3] = ffma2(av[i], b1.y, acc2[i][3]);
            }
        }
    }

#pragma unroll
    for (int i = 0; i < 4; ++i) {
        ull inv2 = bcast2(1.f / l_i[i]);
        int t = q0 + ty * 4 + i;
        float* yp = y + (size_t)t * D_MODEL + hq * DH;
        ulonglong2 o0, o1;
        o0.x = mul2(acc2[i][0], inv2); o0.y = mul2(acc2[i][1], inv2);
        o1.x = mul2(acc2[i][2], inv2); o1.y = mul2(acc2[i][3], inv2);
        *(ulonglong2*)(yp + tx * 4)      = o0;
        *(ulonglong2*)(yp + 64 + tx * 4) = o1;
    }
}

// ---------------------------------------------------------------------------
extern "C" void kernel_launch(void* const* d_in, const int* in_sizes, int n_in,
                              void* d_out, int out_size) {
    const float* x  = (const float*)d_in[0];
    const float* Wq = (const float*)d_in[1];
    const float* Wk = (const float*)d_in[2];
    const float* Wv = (const float*)d_in[3];
    const float* Wo = (const float*)d_in[4];
    float* out = (float*)d_out;

    void *pq, *pk, *pv, *py;
    cudaGetSymbolAddress(&pq, g_q);
    cudaGetSymbolAddress(&pk, g_k);
    cudaGetSymbolAddress(&pv, g_v);
    cudaGetSymbolAddress(&py, g_y);
    float* q = (float*)pq;
    float* kf = (float*)pk;
    float* vf = (float*)pv;
    float* y = (float*)py;

    // Projections (tf32 tensor cores, pipelined)
    sgemm_tf32<<<dim3(D_MODEL / 128, T_SEQ / 128), 256>>>(x, Wq, q, T_SEQ, D_MODEL, D_MODEL);
    sgemm_tf32<<<dim3(KV_DIM / 128, T_SEQ / 128), 256>>>(x, Wk, kf, T_SEQ, KV_DIM, D_MODEL);
    sgemm_tf32<<<dim3(KV_DIM / 128, T_SEQ / 128), 256>>>(x, Wv, vf, T_SEQ, KV_DIM, D_MODEL);

    // RoPE
    {
        int nq = T_SEQ * N_HEADS * HALF;
        rope_kernel<<<(nq + 255) / 256, 256>>>(q, N_HEADS, D_MODEL);
        int nk = T_SEQ * N_KV * HALF;
        rope_kernel<<<(nk + 255) / 256, 256>>>(kf, N_KV, KV_DIM);
    }

    // Attention (R3 FFMA flash kernel)
    cudaFuncSetAttribute(attn_kernel, cudaFuncAttributeMaxDynamicSharedMemorySize, SMEM_BYTES);
    attn_kernel<<<dim3(T_SEQ / 64, N_HEADS), 256, SMEM_BYTES>>>(q, kf, vf, y);

    // Output projection
    sgemm_tf32<<<dim3(D_MODEL / 128, T_SEQ / 128), 256>>>(y, Wo, out, T_SEQ, D_MODEL, D_MODEL);
}

// round 9
// speedup vs baseline: 3.4652x; 1.5597x over previous
#include <cuda_runtime.h>
#include <cuda_fp16.h>
#include <math.h>
#include <cstdint>

// Problem constants
#define T_SEQ 4096
#define D_MODEL 2048
#define N_HEADS 16
#define N_KV 4
#define DH 128
#define HALF 64
#define KV_DIM 512   // N_KV * DH

typedef unsigned long long ull;

// Scratch (device globals; no allocation allowed)
__device__ float g_q[T_SEQ * D_MODEL];
__device__ float g_k[T_SEQ * KV_DIM];
__device__ float g_v[T_SEQ * KV_DIM];
__device__ float g_y[T_SEQ * D_MODEL];

// ---------------------------------------------------------------------------
// Packed f32x2 helpers
// ---------------------------------------------------------------------------
__device__ __forceinline__ ull ffma2(ull a, ull b, ull c) {
    ull d;
    asm("fma.rn.f32x2 %0, %1, %2, %3;" : "=l"(d) : "l"(a), "l"(b), "l"(c));
    return d;
}
__device__ __forceinline__ ull mul2(ull a, ull b) {
    ull d;
    asm("mul.rn.f32x2 %0, %1, %2;" : "=l"(d) : "l"(a), "l"(b));
    return d;
}
__device__ __forceinline__ ull bcast2(float x) {
    ull d;
    asm("mov.b64 %0, {%1, %1};" : "=l"(d) : "f"(x));
    return d;
}

// ---------------------------------------------------------------------------
// fp16 mma.sync helpers (m16n8k16, fp32 accumulate; plain sm_80+ PTX)
// ---------------------------------------------------------------------------
__device__ __forceinline__ uint32_t pack2h(float lo, float hi) {
    __half2 h = __floats2half2_rn(lo, hi);   // .x = lo -> low 16 bits
    return *(uint32_t*)&h;
}

__device__ __forceinline__ void mma_f16(float* d, const uint32_t* a,
                                        const uint32_t* b, const float* c) {
    asm volatile(
        "mma.sync.aligned.m16n8k16.row.col.f32.f16.f16.f32 "
        "{%0,%1,%2,%3}, {%4,%5,%6,%7}, {%8,%9}, {%10,%11,%12,%13};"
        : "=f"(d[0]), "=f"(d[1]), "=f"(d[2]), "=f"(d[3])
        : "r"(a[0]), "r"(a[1]), "r"(a[2]), "r"(a[3]),
          "r"(b[0]), "r"(b[1]),
          "f"(c[0]), "f"(c[1]), "f"(c[2]), "f"(c[3]));
}

// ---------------------------------------------------------------------------
// FP16 tensor-core GEMM, software-pipelined. C[M,N] = A[M,K] @ B[K,N], fp32 io.
// CTA 128x128, BK=16, 256 threads = 8 warps (4m x 2n), warp tile 32x64.
// Smem: packed half2 k-pairs, stride 12 u32 -> conflict-free fragment LDS.
// ---------------------------------------------------------------------------
__global__ __launch_bounds__(256, 2)
void sgemm_f16(const float* __restrict__ A, const float* __restrict__ B,
               float* __restrict__ C, int M, int N, int K) {
    __shared__ uint32_t As[2][128][12];   // [buf][m][k2], k2 = k/2 (0..7) + pad
    __shared__ uint32_t Bs[2][128][12];   // [buf][n][k2]  (B transposed)

    const int tid = threadIdx.x;
    const int wid = tid >> 5;
    const int lane = tid & 31;
    const int g = lane >> 2;
    const int t = lane & 3;
    const int m0 = blockIdx.y * 128;
    const int n0 = blockIdx.x * 128;
    const int wm = (wid & 3) * 32;
    const int wn = (wid >> 2) * 64;

    // staging indices
    const int aRow = tid >> 2;            // 0..63 (and +64)
    const int aK4  = (tid & 3) << 2;      // k offset 0,4,8,12
    const int aK2  = (tid & 3) << 1;      // k2 offset 0,2,4,6
    const int bN   = tid & 127;           // 0..127
    const int bKh  = tid >> 7;            // 0..1

    float acc[2][8][4];
#pragma unroll
    for (int mt = 0; mt < 2; ++mt)
#pragma unroll
        for (int nt = 0; nt < 8; ++nt)
#pragma unroll
            for (int r = 0; r < 4; ++r) acc[mt][nt][r] = 0.f;

    float4 ar[2];
    float  bv[4][2];

    // ---- prologue: load + stage tile 0
#pragma unroll
    for (int l = 0; l < 2; ++l)
        ar[l] = *(const float4*)(A + (size_t)(m0 + aRow + l * 64) * K + aK4);
#pragma unroll
    for (int l = 0; l < 4; ++l) {
        int k2 = bKh + 2 * l;             // 0..7
        bv[l][0] = B[(size_t)(2 * k2) * N + n0 + bN];
        bv[l][1] = B[(size_t)(2 * k2 + 1) * N + n0 + bN];
    }
#pragma unroll
    for (int l = 0; l < 2; ++l) {
        uint2 u = make_uint2(pack2h(ar[l].x, ar[l].y), pack2h(ar[l].z, ar[l].w));
        *(uint2*)(&As[0][aRow + l * 64][aK2]) = u;
    }
#pragma unroll
    for (int l = 0; l < 4; ++l)
        Bs[0][bN][bKh + 2 * l] = pack2h(bv[l][0], bv[l][1]);
    __syncthreads();

    const int KT = K >> 4;
    for (int kt = 0; kt < KT; ++kt) {
        const int buf = kt & 1;

        // ---- prefetch tile kt+1
        if (kt + 1 < KT) {
            const int k0n = (kt + 1) << 4;
#pragma unroll
            for (int l = 0; l < 2; ++l)
                ar[l] = *(const float4*)(A + (size_t)(m0 + aRow + l * 64) * K + k0n + aK4);
#pragma unroll
            for (int l = 0; l < 4; ++l) {
                int k2 = bKh + 2 * l;
                bv[l][0] = B[(size_t)(k0n + 2 * k2) * N + n0 + bN];
                bv[l][1] = B[(size_t)(k0n + 2 * k2 + 1) * N + n0 + bN];
            }
        }

        // ---- compute tile kt: one k16 step, 16 HMMA per warp
        uint32_t af[2][4];
#pragma unroll
        for (int mt = 0; mt < 2; ++mt) {
            const int r0 = wm + mt * 16;
            af[mt][0] = As[buf][r0 + g][t];
            af[mt][1] = As[buf][r0 + g + 8][t];
            af[mt][2] = As[buf][r0 + g][4 + t];
            af[mt][3] = As[buf][r0 + g + 8][4 + t];
        }
#pragma unroll
        for (int nt = 0; nt < 8; ++nt) {
            const int n = wn + nt * 8 + g;
            uint32_t bf[2] = {Bs[buf][n][t], Bs[buf][n][4 + t]};
#pragma unroll
            for (int mt = 0; mt < 2; ++mt)
                mma_f16(acc[mt][nt], af[mt], bf, acc[mt][nt]);
        }

        // ---- stage tile kt+1
        if (kt + 1 < KT) {
            const int nb = buf ^ 1;
#pragma unroll
            for (int l = 0; l < 2; ++l) {
                uint2 u = make_uint2(pack2h(ar[l].x, ar[l].y), pack2h(ar[l].z, ar[l].w));
                *(uint2*)(&As[nb][aRow + l * 64][aK2]) = u;
            }
#pragma unroll
            for (int l = 0; l < 4; ++l)
                Bs[nb][bN][bKh + 2 * l] = pack2h(bv[l][0], bv[l][1]);
            __syncthreads();
        }
    }

    // ---- epilogue
#pragma unroll
    for (int mt = 0; mt < 2; ++mt) {
        const int r0 = m0 + wm + mt * 16;
#pragma unroll
        for (int nt = 0; nt < 8; ++nt) {
            const int c0 = n0 + wn + nt * 8 + t * 2;
            *(float2*)(C + (size_t)(r0 + g) * N + c0) =
                make_float2(acc[mt][nt][0], acc[mt][nt][1]);
            *(float2*)(C + (size_t)(r0 + g + 8) * N + c0) =
                make_float2(acc[mt][nt][2], acc[mt][nt][3]);
        }
    }
}

// ---------------------------------------------------------------------------
// RoPE in-place on [T, nheads, 128] buffers (rowstride = nheads*128)
// ---------------------------------------------------------------------------
__global__ void rope_kernel(float* __restrict__ buf, int nheads, int rowstride) {
    int idx = blockIdx.x * blockDim.x + threadIdx.x;
    int total = T_SEQ * nheads * HALF;
    if (idx >= total) return;
    int i = idx & (HALF - 1);
    int h = (idx >> 6) % nheads;
    int t = idx / (HALF * nheads);

    float inv = powf(10000.f, -(float)i / (float)HALF);
    float ang = (float)t * inv;
    float s, c;
    sincosf(ang, &s, &c);

    float* base = buf + (size_t)t * rowstride + h * DH;
    float x1 = base[i];
    float x2 = base[i + HALF];
    base[i]        = x1 * c - x2 * s;
    base[i + HALF] = x1 * s + x2 * c;
}

// ---------------------------------------------------------------------------
// Flash attention v3: S = QK^T via fp16 mma (smem roundtrip), softmax + exact
// fp32 PV identical to the proven R3 kernel. CTA = 64 queries x 1 head,
// 256 threads, 64-key blocks.
// Smem (u32 units): Qh[64][68] fp16-pairs, Kh[64][68], Vs fp32 [64][128],
// SP fp32 [64][68] (shared between S and P^T).
// ---------------------------------------------------------------------------
#define OQ  0
#define OK_ 4352
#define OV  8704
#define OS  16896
#define ATTN_SMEM_U32 21248
#define ATTN_SMEM_BYTES (ATTN_SMEM_U32 * 4)

__global__ __launch_bounds__(256)
void attn_kernel(const float* __restrict__ q, const float* __restrict__ k,
                 const float* __restrict__ v, float* __restrict__ y) {
    extern __shared__ uint32_t smu[];
    uint32_t* Qh = smu + OQ;
    uint32_t* Kh = smu + OK_;
    float*    Vs = (float*)(smu + OV);
    float*    SP = (float*)(smu + OS);

    const int qb = blockIdx.x;
    const int hq = blockIdx.y;
    const int hkv = hq >> 2;
    const int tid = threadIdx.x;
    const int tx = tid & 15;
    const int ty = tid >> 4;
    const int wid = tid >> 5;
    const int lane = tid & 31;
    const int g = lane >> 2;
    const int t = lane & 3;
    const int q0 = qb * 64;
    const int mt = wid & 3;          // S warp tile: query 16-row group
    const int nh = wid >> 2;         // S warp tile: key 32-col half

    // ---- stage Q as fp16 pairs (once per CTA)
#pragma unroll
    for (int l = 0; l < 8; ++l) {
        int lin = tid + l * 256;
        int row = lin >> 5;
        int d4 = lin & 31;
        float4 val = *(const float4*)(q + (size_t)(q0 + row) * D_MODEL + hq * DH + d4 * 4);
        uint2 u = make_uint2(pack2h(val.x, val.y), pack2h(val.z, val.w));
        *(uint2*)(Qh + row * 68 + d4 * 2) = u;
    }

    float m_i[4], l_i[4];
    ull acc2[4][4];
#pragma unroll
    for (int i = 0; i < 4; ++i) {
        m_i[i] = -1e30f;
        l_i[i] = 0.f;
#pragma unroll
        for (int j = 0; j < 4; ++j) acc2[i][j] = 0ull;
    }

    const float scale = 0.08838834764831845f;   // 1/sqrt(128)

    for (int jb = 0; jb <= qb; ++jb) {
        const int j0 = jb * 64;
        __syncthreads();   // protect Kh/Vs/SP from previous iteration readers

        // ---- stage K (fp16 pairs) + V (fp32)
#pragma unroll
        for (int l = 0; l < 8; ++l) {
            int lin = tid + l * 256;
            int row = lin >> 5;
            int d4 = lin & 31;
            float4 kv = *(const float4*)(k + (size_t)(j0 + row) * KV_DIM + hkv * DH + d4 * 4);
            uint2 u = make_uint2(pack2h(kv.x, kv.y), pack2h(kv.z, kv.w));
            *(uint2*)(Kh + row * 68 + d4 * 2) = u;
            float4 vv = *(const float4*)(v + (size_t)(j0 + row) * KV_DIM + hkv * DH + d4 * 4);
            *(float4*)(Vs + row * 128 + d4 * 4) = vv;
        }
        __syncthreads();

        // ---- S = Q K^T via fp16 mma: warp (mt, nh) -> m16 x n32 tile
        {
            float sf[4][4];
#pragma unroll
            for (int nt = 0; nt < 4; ++nt)
#pragma unroll
                for (int r = 0; r < 4; ++r) sf[nt][r] = 0.f;

            const uint32_t* qr = Qh + (mt * 16) * 68;
            const uint32_t* kr = Kh + (nh * 32) * 68;
#pragma unroll
            for (int ks = 0; ks < 8; ++ks) {
                const int kk2 = ks * 8;
                uint32_t a[4] = {qr[g * 68 + kk2 + t],
                                 qr[(g + 8) * 68 + kk2 + t],
                                 qr[g * 68 + kk2 + 4 + t],
                                 qr[(g + 8) * 68 + kk2 + 4 + t]};
#pragma unroll
                for (int nt = 0; nt < 4; ++nt) {
                    uint32_t b[2] = {kr[(nt * 8 + g) * 68 + kk2 + t],
                                     kr[(nt * 8 + g) * 68 + kk2 + 4 + t]};
                    mma_f16(sf[nt], a, b, sf[nt]);
                }
            }
            // write S fragments to SP[query][key]
#pragma unroll
            for (int nt = 0; nt < 4; ++nt) {
                const int row0 = mt * 16 + g;
                const int col = nh * 32 + nt * 8 + 2 * t;
                *(float2*)(SP + row0 * 68 + col) = make_float2(sf[nt][0], sf[nt][1]);
                *(float2*)(SP + (row0 + 8) * 68 + col) = make_float2(sf[nt][2], sf[nt][3]);
            }
        }
        __syncthreads();

        // ---- read S block (R3 layout), scale + causal mask
        float s[4][4];
        const bool diag = (jb == qb);
#pragma unroll
        for (int i = 0; i < 4; ++i) {
            float4 r4 = *(float4*)(SP + (ty * 4 + i) * 68 + tx * 4);
            s[i][0] = r4.x; s[i][1] = r4.y; s[i][2] = r4.z; s[i][3] = r4.w;
            int rl = ty * 4 + i;
#pragma unroll
            for (int j = 0; j < 4; ++j) {
                int cl = tx * 4 + j;
                float sv = s[i][j] * scale;
                if (diag && cl > rl) sv = -1e30f;
                s[i][j] = sv;
            }
        }

        // ---- online softmax per row (rows shared across the 16 tx lanes)
#pragma unroll
        for (int i = 0; i < 4; ++i) {
            float mx = fmaxf(fmaxf(s[i][0], s[i][1]), fmaxf(s[i][2], s[i][3]));
#pragma unroll
            for (int off = 1; off < 16; off <<= 1)
                mx = fmaxf(mx, __shfl_xor_sync(0xffffffffu, mx, off));
            float mnew = fmaxf(m_i[i], mx);
            float alpha = __expf(m_i[i] - mnew);
            float rs = 0.f;
#pragma unroll
            for (int j = 0; j < 4; ++j) {
                float p = __expf(s[i][j] - mnew);
                s[i][j] = p;
                rs += p;
            }
#pragma unroll
            for (int off = 1; off < 16; off <<= 1)
                rs += __shfl_xor_sync(0xffffffffu, rs, off);
            l_i[i] = l_i[i] * alpha + rs;
            m_i[i] = mnew;
            ull al2 = bcast2(alpha);
#pragma unroll
            for (int j = 0; j < 4; ++j) acc2[i][j] = mul2(acc2[i][j], al2);
        }
        __syncthreads();   // all S reads done before SP is overwritten with P^T

        // ---- write P transposed: SP[key][query]
#pragma unroll
        for (int j = 0; j < 4; ++j) {
            *(float4*)(SP + (tx * 4 + j) * 68 + ty * 4) =
                make_float4(s[0][j], s[1][j], s[2][j], s[3][j]);
        }
        __syncthreads();

        // ---- O += P V  (exact fp32, f32x2 packed)
#pragma unroll 4
        for (int c = 0; c < 64; ++c) {
            float4 a = *(float4*)(SP + c * 68 + ty * 4);
            ulonglong2 b0 = *(ulonglong2*)(Vs + c * 128 + tx * 4);
            ulonglong2 b1 = *(ulonglong2*)(Vs + c * 128 + 64 + tx * 4);
            ull av[4] = {bcast2(a.x), bcast2(a.y), bcast2(a.z), bcast2(a.w)};
#pragma unroll
            for (int i = 0; i < 4; ++i) {
                acc2[i][0] = ffma2(av[i], b0.x, acc2[i][0]);
                acc2[i][1] = ffma2(av[i], b0.y, acc2[i][1]);
                acc2[i][2] = ffma2(av[i], b1.x, acc2[i][2]);
                acc2[i][3] = ffma2(av[i], b1.y, acc2[i][3]);
            }
        }
    }

    // ---- normalize & write y[t, hq*128 + dd]
#pragma unroll
    for (int i = 0; i < 4; ++i) {
        ull inv2 = bcast2(1.f / l_i[i]);
        int tq = q0 + ty * 4 + i;
        float* yp = y + (size_t)tq * D_MODEL + hq * DH;
        ulonglong2 o0, o1;
        o0.x = mul2(acc2[i][0], inv2); o0.y = mul2(acc2[i][1], inv2);
        o1.x = mul2(acc2[i][2], inv2); o1.y = mul2(acc2[i][3], inv2);
        *(ulonglong2*)(yp + tx * 4)      = o0;
        *(ulonglong2*)(yp + 64 + tx * 4) = o1;
    }
}

// ---------------------------------------------------------------------------
extern "C" void kernel_launch(void* const* d_in, const int* in_sizes, int n_in,
                              void* d_out, int out_size) {
    const float* x  = (const float*)d_in[0];
    const float* Wq = (const float*)d_in[1];
    const float* Wk = (const float*)d_in[2];
    const float* Wv = (const float*)d_in[3];
    const float* Wo = (const float*)d_in[4];
    float* out = (float*)d_out;

    void *pq, *pk, *pv, *py;
    cudaGetSymbolAddress(&pq, g_q);
    cudaGetSymbolAddress(&pk, g_k);
    cudaGetSymbolAddress(&pv, g_v);
    cudaGetSymbolAddress(&py, g_y);
    float* q = (float*)pq;
    float* kf = (float*)pk;
    float* vf = (float*)pv;
    float* y = (float*)py;

    // Projections (fp16 tensor cores, pipelined)
    sgemm_f16<<<dim3(D_MODEL / 128, T_SEQ / 128), 256>>>(x, Wq, q, T_SEQ, D_MODEL, D_MODEL);
    sgemm_f16<<<dim3(KV_DIM / 128, T_SEQ / 128), 256>>>(x, Wk, kf, T_SEQ, KV_DIM, D_MODEL);
    sgemm_f16<<<dim3(KV_DIM / 128, T_SEQ / 128), 256>>>(x, Wv, vf, T_SEQ, KV_DIM, D_MODEL);

    // RoPE
    {
        int nq = T_SEQ * N_HEADS * HALF;
        rope_kernel<<<(nq + 255) / 256, 256>>>(q, N_HEADS, D_MODEL);
        int nk = T_SEQ * N_KV * HALF;
        rope_kernel<<<(nk + 255) / 256, 256>>>(kf, N_KV, KV_DIM);
    }

    // Attention (fp16 mma S, exact fp32 PV)
    cudaFuncSetAttribute(attn_kernel, cudaFuncAttributeMaxDynamicSharedMemorySize, ATTN_SMEM_BYTES);
    attn_kernel<<<dim3(T_SEQ / 64, N_HEADS), 256, ATTN_SMEM_BYTES>>>(q, kf, vf, y);

    // Output projection
    sgemm_f16<<<dim3(D_MODEL / 128, T_SEQ / 128), 256>>>(y, Wo, out, T_SEQ, D_MODEL, D_MODEL);
}

// round 10
// speedup vs baseline: 6.7215x; 1.9397x over previous
#include <cuda_runtime.h>
#include <cuda_fp16.h>
#include <math.h>
#include <cstdint>

// Problem constants
#define T_SEQ 4096
#define D_MODEL 2048
#define N_HEADS 16
#define N_KV 4
#define DH 128
#define HALF 64
#define KV_DIM 512   // N_KV * DH

typedef unsigned long long ull;

// Scratch (device globals; no allocation allowed)
__device__ float g_q[T_SEQ * D_MODEL];
__device__ float g_k[T_SEQ * KV_DIM];
__device__ float g_v[T_SEQ * KV_DIM];
__device__ float g_y[T_SEQ * D_MODEL];

// ---------------------------------------------------------------------------
// helpers
// ---------------------------------------------------------------------------
__device__ __forceinline__ uint32_t pack2h(float lo, float hi) {
    __half2 h = __floats2half2_rn(lo, hi);   // .x = lo -> low 16 bits
    return *(uint32_t*)&h;
}

__device__ __forceinline__ void mma_f16(float* d, const uint32_t* a,
                                        const uint32_t* b, const float* c) {
    asm volatile(
        "mma.sync.aligned.m16n8k16.row.col.f32.f16.f16.f32 "
        "{%0,%1,%2,%3}, {%4,%5,%6,%7}, {%8,%9}, {%10,%11,%12,%13};"
        : "=f"(d[0]), "=f"(d[1]), "=f"(d[2]), "=f"(d[3])
        : "r"(a[0]), "r"(a[1]), "r"(a[2]), "r"(a[3]),
          "r"(b[0]), "r"(b[1]),
          "f"(c[0]), "f"(c[1]), "f"(c[2]), "f"(c[3]));
}

__device__ __forceinline__ uint32_t smem_u32(const void* p) {
    uint32_t a;
    asm("{ .reg .u64 t; cvta.to.shared.u64 t, %1; cvt.u32.u64 %0, t; }" : "=r"(a) : "l"(p));
    return a;
}

__device__ __forceinline__ void ldmx4t(uint32_t& b0, uint32_t& b1,
                                       uint32_t& b2, uint32_t& b3, uint32_t addr) {
    asm volatile("ldmatrix.sync.aligned.m8n8.x4.trans.shared.b16 {%0,%1,%2,%3}, [%4];"
                 : "=r"(b0), "=r"(b1), "=r"(b2), "=r"(b3) : "r"(addr));
}

// ---------------------------------------------------------------------------
// FP16 tensor-core GEMM, software-pipelined (unchanged from R9).
// ---------------------------------------------------------------------------
__global__ __launch_bounds__(256, 2)
void sgemm_f16(const float* __restrict__ A, const float* __restrict__ B,
               float* __restrict__ C, int M, int N, int K) {
    __shared__ uint32_t As[2][128][12];
    __shared__ uint32_t Bs[2][128][12];

    const int tid = threadIdx.x;
    const int wid = tid >> 5;
    const int lane = tid & 31;
    const int g = lane >> 2;
    const int t = lane & 3;
    const int m0 = blockIdx.y * 128;
    const int n0 = blockIdx.x * 128;
    const int wm = (wid & 3) * 32;
    const int wn = (wid >> 2) * 64;

    const int aRow = tid >> 2;
    const int aK4  = (tid & 3) << 2;
    const int aK2  = (tid & 3) << 1;
    const int bN   = tid & 127;
    const int bKh  = tid >> 7;

    float acc[2][8][4];
#pragma unroll
    for (int mt = 0; mt < 2; ++mt)
#pragma unroll
        for (int nt = 0; nt < 8; ++nt)
#pragma unroll
            for (int r = 0; r < 4; ++r) acc[mt][nt][r] = 0.f;

    float4 ar[2];
    float  bv[4][2];

#pragma unroll
    for (int l = 0; l < 2; ++l)
        ar[l] = *(const float4*)(A + (size_t)(m0 + aRow + l * 64) * K + aK4);
#pragma unroll
    for (int l = 0; l < 4; ++l) {
        int k2 = bKh + 2 * l;
        bv[l][0] = B[(size_t)(2 * k2) * N + n0 + bN];
        bv[l][1] = B[(size_t)(2 * k2 + 1) * N + n0 + bN];
    }
#pragma unroll
    for (int l = 0; l < 2; ++l) {
        uint2 u = make_uint2(pack2h(ar[l].x, ar[l].y), pack2h(ar[l].z, ar[l].w));
        *(uint2*)(&As[0][aRow + l * 64][aK2]) = u;
    }
#pragma unroll
    for (int l = 0; l < 4; ++l)
        Bs[0][bN][bKh + 2 * l] = pack2h(bv[l][0], bv[l][1]);
    __syncthreads();

    const int KT = K >> 4;
    for (int kt = 0; kt < KT; ++kt) {
        const int buf = kt & 1;

        if (kt + 1 < KT) {
            const int k0n = (kt + 1) << 4;
#pragma unroll
            for (int l = 0; l < 2; ++l)
                ar[l] = *(const float4*)(A + (size_t)(m0 + aRow + l * 64) * K + k0n + aK4);
#pragma unroll
            for (int l = 0; l < 4; ++l) {
                int k2 = bKh + 2 * l;
                bv[l][0] = B[(size_t)(k0n + 2 * k2) * N + n0 + bN];
                bv[l][1] = B[(size_t)(k0n + 2 * k2 + 1) * N + n0 + bN];
            }
        }

        uint32_t af[2][4];
#pragma unroll
        for (int mt = 0; mt < 2; ++mt) {
            const int r0 = wm + mt * 16;
            af[mt][0] = As[buf][r0 + g][t];
            af[mt][1] = As[buf][r0 + g + 8][t];
            af[mt][2] = As[buf][r0 + g][4 + t];
            af[mt][3] = As[buf][r0 + g + 8][4 + t];
        }
#pragma unroll
        for (int nt = 0; nt < 8; ++nt) {
            const int n = wn + nt * 8 + g;
            uint32_t bf[2] = {Bs[buf][n][t], Bs[buf][n][4 + t]};
#pragma unroll
            for (int mt = 0; mt < 2; ++mt)
                mma_f16(acc[mt][nt], af[mt], bf, acc[mt][nt]);
        }

        if (kt + 1 < KT) {
            const int nb = buf ^ 1;
#pragma unroll
            for (int l = 0; l < 2; ++l) {
                uint2 u = make_uint2(pack2h(ar[l].x, ar[l].y), pack2h(ar[l].z, ar[l].w));
                *(uint2*)(&As[nb][aRow + l * 64][aK2]) = u;
            }
#pragma unroll
            for (int l = 0; l < 4; ++l)
                Bs[nb][bN][bKh + 2 * l] = pack2h(bv[l][0], bv[l][1]);
            __syncthreads();
        }
    }

#pragma unroll
    for (int mt = 0; mt < 2; ++mt) {
        const int r0 = m0 + wm + mt * 16;
#pragma unroll
        for (int nt = 0; nt < 8; ++nt) {
            const int c0 = n0 + wn + nt * 8 + t * 2;
            *(float2*)(C + (size_t)(r0 + g) * N + c0) =
                make_float2(acc[mt][nt][0], acc[mt][nt][1]);
            *(float2*)(C + (size_t)(r0 + g + 8) * N + c0) =
                make_float2(acc[mt][nt][2], acc[mt][nt][3]);
        }
    }
}

// ---------------------------------------------------------------------------
// RoPE in-place on [T, nheads, 128] buffers (rowstride = nheads*128)
// ---------------------------------------------------------------------------
__global__ void rope_kernel(float* __restrict__ buf, int nheads, int rowstride) {
    int idx = blockIdx.x * blockDim.x + threadIdx.x;
    int total = T_SEQ * nheads * HALF;
    if (idx >= total) return;
    int i = idx & (HALF - 1);
    int h = (idx >> 6) % nheads;
    int t = idx / (HALF * nheads);

    float inv = powf(10000.f, -(float)i / (float)HALF);
    float ang = (float)t * inv;
    float s, c;
    sincosf(ang, &s, &c);

    float* base = buf + (size_t)t * rowstride + h * DH;
    float x1 = base[i];
    float x2 = base[i + HALF];
    base[i]        = x1 * c - x2 * s;
    base[i + HALF] = x1 * s + x2 * c;
}

// ---------------------------------------------------------------------------
// Flash attention v4 (FA2-style, all fp16 mma):
//   S = QK^T (fp16 mma) -> softmax in fragment registers -> P packed straight
//   into A-fragments -> O += P V via mma with V B-fragments from
//   ldmatrix.x4.trans. CTA = 64 queries x 1 head, 128 threads / 4 warps,
//   warp = 16 q rows x full d=128.
// Smem (u32): Qh[64][68] pairs, Kh[64][68] pairs, Vh fp16 [64][136].
// ---------------------------------------------------------------------------
#define AOQ 0
#define AOK 4352
#define AOV 8704
#define ATTN_SMEM_BYTES ((8704 + 4352) * 4)   // 52224

__global__ __launch_bounds__(128)
void attn_kernel(const float* __restrict__ q, const float* __restrict__ k,
                 const float* __restrict__ v, float* __restrict__ y) {
    extern __shared__ uint32_t smu[];
    uint32_t* Qh = smu + AOQ;              // [64][68] half2 pairs along d
    uint32_t* Kh = smu + AOK;              // [64][68]
    __half*   Vh = (__half*)(smu + AOV);   // [64][136] row-major [key][d]

    const int qb = blockIdx.x;
    const int hq = blockIdx.y;
    const int hkv = hq >> 2;
    const int q0 = qb * 64;
    const int tid = threadIdx.x;
    const int wid = tid >> 5;
    const int lane = tid & 31;
    const int g = lane >> 2;
    const int t = lane & 3;
    const int r0 = wid * 16;               // warp's q-row group
    const int rg0 = q0 + r0 + g;
    const int rg1 = rg0 + 8;

    // ---- stage Q once (fp32 -> fp16 pairs)
#pragma unroll
    for (int l = 0; l < 16; ++l) {
        int lin = tid + l * 128;
        int row = lin >> 5;
        int d4 = lin & 31;
        float4 val = *(const float4*)(q + (size_t)(q0 + row) * D_MODEL + hq * DH + d4 * 4);
        *(uint2*)(Qh + row * 68 + d4 * 2) =
            make_uint2(pack2h(val.x, val.y), pack2h(val.z, val.w));
    }

    float acc[16][4];                      // O: rows {g,g+8} x d cols
#pragma unroll
    for (int n = 0; n < 16; ++n)
#pragma unroll
        for (int r = 0; r < 4; ++r) acc[n][r] = 0.f;
    float m_i[2] = {-1e30f, -1e30f};
    float l_i[2] = {0.f, 0.f};

    const float scale = 0.08838834764831845f;   // 1/sqrt(128)

    for (int jb = 0; jb <= qb; ++jb) {
        const int j0 = jb * 64;
        __syncthreads();   // previous tile fully consumed

        // ---- stage K (pairs) + V (fp16 row-major)
#pragma unroll
        for (int l = 0; l < 16; ++l) {
            int lin = tid + l * 128;
            int row = lin >> 5;
            int d4 = lin & 31;
            float4 kv = *(const float4*)(k + (size_t)(j0 + row) * KV_DIM + hkv * DH + d4 * 4);
            *(uint2*)(Kh + row * 68 + d4 * 2) =
                make_uint2(pack2h(kv.x, kv.y), pack2h(kv.z, kv.w));
            float4 vv = *(const float4*)(v + (size_t)(j0 + row) * KV_DIM + hkv * DH + d4 * 4);
            *(uint2*)(Vh + row * 136 + d4 * 4) =
                make_uint2(pack2h(vv.x, vv.y), pack2h(vv.z, vv.w));
        }
        __syncthreads();

        if (j0 > q0 + r0 + 15) continue;   // warp fully above this key block

        // ---- S = Q K^T : 8 n-tiles (64 keys), 8 k16 steps (d=128)
        float sf[8][4];
#pragma unroll
        for (int nt = 0; nt < 8; ++nt)
#pragma unroll
            for (int r = 0; r < 4; ++r) sf[nt][r] = 0.f;

        const uint32_t* qr0 = Qh + (r0 + g) * 68;
        const uint32_t* qr1 = Qh + (r0 + g + 8) * 68;
#pragma unroll
        for (int ks = 0; ks < 8; ++ks) {
            const int kk = ks * 8;
            uint32_t a[4] = {qr0[kk + t], qr1[kk + t], qr0[kk + 4 + t], qr1[kk + 4 + t]};
#pragma unroll
            for (int nt = 0; nt < 8; ++nt) {
                const uint32_t* kr = Kh + (nt * 8 + g) * 68 + kk;
                uint32_t b[2] = {kr[t], kr[4 + t]};
                mma_f16(sf[nt], a, b, sf[nt]);
            }
        }

        // ---- scale + causal mask (diagonal band only)
#pragma unroll
        for (int nt = 0; nt < 8; ++nt) {
            sf[nt][0] *= scale; sf[nt][1] *= scale;
            sf[nt][2] *= scale; sf[nt][3] *= scale;
        }
        if (j0 + 63 > rg0) {
#pragma unroll
            for (int nt = 0; nt < 8; ++nt) {
                const int c = j0 + nt * 8 + 2 * t;
                if (c     > rg0) sf[nt][0] = -1e30f;
                if (c + 1 > rg0) sf[nt][1] = -1e30f;
                if (c     > rg1) sf[nt][2] = -1e30f;
                if (c + 1 > rg1) sf[nt][3] = -1e30f;
            }
        }

        // ---- online softmax (quad-local: lanes sharing g differ only in t)
        float mx0 = -1e30f, mx1 = -1e30f;
#pragma unroll
        for (int nt = 0; nt < 8; ++nt) {
            mx0 = fmaxf(mx0, fmaxf(sf[nt][0], sf[nt][1]));
            mx1 = fmaxf(mx1, fmaxf(sf[nt][2], sf[nt][3]));
        }
        mx0 = fmaxf(mx0, __shfl_xor_sync(0xffffffffu, mx0, 1));
        mx0 = fmaxf(mx0, __shfl_xor_sync(0xffffffffu, mx0, 2));
        mx1 = fmaxf(mx1, __shfl_xor_sync(0xffffffffu, mx1, 1));
        mx1 = fmaxf(mx1, __shfl_xor_sync(0xffffffffu, mx1, 2));

        const float mn0 = fmaxf(m_i[0], mx0);
        const float mn1 = fmaxf(m_i[1], mx1);
        const float al0 = __expf(m_i[0] - mn0);
        const float al1 = __expf(m_i[1] - mn1);

        float sum0 = 0.f, sum1 = 0.f;
#pragma unroll
        for (int nt = 0; nt < 8; ++nt) {
            sf[nt][0] = __expf(sf[nt][0] - mn0);
            sf[nt][1] = __expf(sf[nt][1] - mn0);
            sf[nt][2] = __expf(sf[nt][2] - mn1);
            sf[nt][3] = __expf(sf[nt][3] - mn1);
            sum0 += sf[nt][0] + sf[nt][1];
            sum1 += sf[nt][2] + sf[nt][3];
        }
        sum0 += __shfl_xor_sync(0xffffffffu, sum0, 1);
        sum0 += __shfl_xor_sync(0xffffffffu, sum0, 2);
        sum1 += __shfl_xor_sync(0xffffffffu, sum1, 1);
        sum1 += __shfl_xor_sync(0xffffffffu, sum1, 2);

        l_i[0] = l_i[0] * al0 + sum0;
        l_i[1] = l_i[1] * al1 + sum1;
        m_i[0] = mn0;
        m_i[1] = mn1;

#pragma unroll
        for (int n = 0; n < 16; ++n) {
            acc[n][0] *= al0; acc[n][1] *= al0;
            acc[n][2] *= al1; acc[n][3] *= al1;
        }

        // ---- O += P V : P packed from fragments, V via ldmatrix.x4.trans
        const int vrow = lane & 15;
        const int vcol8 = (lane >> 4) * 8;
#pragma unroll
        for (int ks = 0; ks < 4; ++ks) {
            uint32_t a[4] = {pack2h(sf[2 * ks][0],     sf[2 * ks][1]),
                             pack2h(sf[2 * ks][2],     sf[2 * ks][3]),
                             pack2h(sf[2 * ks + 1][0], sf[2 * ks + 1][1]),
                             pack2h(sf[2 * ks + 1][2], sf[2 * ks + 1][3])};
            const __half* vbase = Vh + (16 * ks + vrow) * 136 + vcol8;
#pragma unroll
            for (int ntp = 0; ntp < 8; ++ntp) {
                uint32_t b0, b1, b2, b3;
                ldmx4t(b0, b1, b2, b3, smem_u32(vbase + ntp * 16));
                uint32_t blo[2] = {b0, b1};
                uint32_t bhi[2] = {b2, b3};
                mma_f16(acc[2 * ntp],     a, blo, acc[2 * ntp]);
                mma_f16(acc[2 * ntp + 1], a, bhi, acc[2 * ntp + 1]);
            }
        }
    }

    // ---- normalize + write y rows rg0, rg1
    const float i0 = 1.f / l_i[0];
    const float i1 = 1.f / l_i[1];
    float* y0 = y + (size_t)rg0 * D_MODEL + hq * DH;
    float* y1 = y + (size_t)rg1 * D_MODEL + hq * DH;
#pragma unroll
    for (int n = 0; n < 16; ++n) {
        const int c0 = n * 8 + 2 * t;
        *(float2*)(y0 + c0) = make_float2(acc[n][0] * i0, acc[n][1] * i0);
        *(float2*)(y1 + c0) = make_float2(acc[n][2] * i1, acc[n][3] * i1);
    }
}

// ---------------------------------------------------------------------------
extern "C" void kernel_launch(void* const* d_in, const int* in_sizes, int n_in,
                              void* d_out, int out_size) {
    const float* x  = (const float*)d_in[0];
    const float* Wq = (const float*)d_in[1];
    const float* Wk = (const float*)d_in[2];
    const float* Wv = (const float*)d_in[3];
    const float* Wo = (const float*)d_in[4];
    float* out = (float*)d_out;

    void *pq, *pk, *pv, *py;
    cudaGetSymbolAddress(&pq, g_q);
    cudaGetSymbolAddress(&pk, g_k);
    cudaGetSymbolAddress(&pv, g_v);
    cudaGetSymbolAddress(&py, g_y);
    float* q = (float*)pq;
    float* kf = (float*)pk;
    float* vf = (float*)pv;
    float* y = (float*)py;

    // Projections (fp16 tensor cores, pipelined)
    sgemm_f16<<<dim3(D_MODEL / 128, T_SEQ / 128), 256>>>(x, Wq, q, T_SEQ, D_MODEL, D_MODEL);
    sgemm_f16<<<dim3(KV_DIM / 128, T_SEQ / 128), 256>>>(x, Wk, kf, T_SEQ, KV_DIM, D_MODEL);
    sgemm_f16<<<dim3(KV_DIM / 128, T_SEQ / 128), 256>>>(x, Wv, vf, T_SEQ, KV_DIM, D_MODEL);

    // RoPE
    {
        int nq = T_SEQ * N_HEADS * HALF;
        rope_kernel<<<(nq + 255) / 256, 256>>>(q, N_HEADS, D_MODEL);
        int nk = T_SEQ * N_KV * HALF;
        rope_kernel<<<(nk + 255) / 256, 256>>>(kf, N_KV, KV_DIM);
    }

    // Attention (all-mma FA2 style)
    cudaFuncSetAttribute(attn_kernel, cudaFuncAttributeMaxDynamicSharedMemorySize, ATTN_SMEM_BYTES);
    attn_kernel<<<dim3(T_SEQ / 64, N_HEADS), 128, ATTN_SMEM_BYTES>>>(q, kf, vf, y);

    // Output projection
    sgemm_f16<<<dim3(D_MODEL / 128, T_SEQ / 128), 256>>>(y, Wo, out, T_SEQ, D_MODEL, D_MODEL);
}